// round 1
// baseline (speedup 1.0000x reference)
#include <cuda_runtime.h>
#include <math.h>

#define BATCH 256
#define SEQT  512
#define EMB   300
#define HID   256
#define GATES 1024   // 4*HID
#define NBLK  128
#define SMEM_RNN (256*128*4 + 32*260*4)   // Wh tile + h tile = 164352 B

// Scratch (static device memory — allocation-free)
__device__ float d_xz[2][SEQT][BATCH][GATES];   // gate-interleaved: [t][b][h*4+g], bias folded in
__device__ float d_hbuf[2][2][BATCH][HID];      // [dir][pingpong][b][h]
__device__ int   d_len[BATCH];
__device__ unsigned g_bar_count;
__device__ unsigned g_bar_sense;

__device__ __forceinline__ float sigf(float x){ return 1.0f/(1.0f + expf(-x)); }

// ---------------------------------------------------------------------------
// Kernel 1: lengths + zero initial states (must re-run every launch)
// ---------------------------------------------------------------------------
__global__ void k_init(const int* __restrict__ ids){
    int b = blockIdx.x;
    __shared__ int cnt;
    if (threadIdx.x == 0) cnt = 0;
    __syncthreads();
    int c = 0;
    for (int t = threadIdx.x; t < SEQT; t += blockDim.x)
        c += (ids[b*SEQT + t] != 0);
    #pragma unroll
    for (int o = 16; o; o >>= 1) c += __shfl_down_sync(0xffffffffu, c, o);
    if ((threadIdx.x & 31) == 0) atomicAdd(&cnt, c);
    __syncthreads();
    if (threadIdx.x == 0) d_len[b] = cnt;
    for (int i = threadIdx.x; i < HID; i += blockDim.x){
        d_hbuf[0][0][b][i] = 0.0f;
        d_hbuf[1][0][b][i] = 0.0f;
    }
}

// ---------------------------------------------------------------------------
// Kernel 2: gathered input GEMM: xz[dir][t][b][:] = emb[ids[b][t]] @ Wx + bias
// M = T*B = 131072 (m = t*256 + b), N = 2*1024, K = 300
// 64x64 tile, BK=8, 256 threads, 4x4 per-thread register tile
// ---------------------------------------------------------------------------
__global__ void k_ingemm(const int* __restrict__ ids,
                         const float* __restrict__ emb,
                         const float* __restrict__ Wfw, const float* __restrict__ bfw,
                         const float* __restrict__ Wbw, const float* __restrict__ bbw){
    __shared__ float As[8][64];
    __shared__ float Bs[8][64];
    __shared__ int rowid[64];
    int m0  = blockIdx.x * 64;
    int nt  = blockIdx.y;           // 0..31
    int dir = nt >> 4;
    int n0  = (nt & 15) * 64;       // column offset within one direction (0..960)
    const float* __restrict__ Wg = dir ? Wbw : Wfw;
    const float* __restrict__ bg = dir ? bbw : bfw;
    int tid = threadIdx.x;

    if (tid < 64){
        int m  = m0 + tid;
        int tt = m >> 8;            // /BATCH
        int bb = m & 255;
        rowid[tid] = ids[bb*SEQT + tt];
    }
    __syncthreads();

    int tx = tid & 15, ty = tid >> 4;
    int arow = tid >> 2;            // 0..63
    int akk  = (tid & 3) * 2;       // 0,2,4,6
    int bk   = tid >> 6;            // 0..3
    int bn   = tid & 63;

    float acc[4][4] = {};
    for (int k0 = 0; k0 < EMB; k0 += 8){
        {
            int row = rowid[arow];
            float vx = 0.0f, vy = 0.0f;
            if (k0 + akk     < EMB) vx = emb[row*EMB + k0 + akk];
            if (k0 + akk + 1 < EMB) vy = emb[row*EMB + k0 + akk + 1];
            As[akk][arow]     = vx;
            As[akk + 1][arow] = vy;
            #pragma unroll
            for (int p = 0; p < 2; p++){
                int kk = bk + p*4;
                float v = 0.0f;
                if (k0 + kk < EMB) v = Wg[(k0 + kk)*GATES + n0 + bn];
                Bs[kk][bn] = v;
            }
        }
        __syncthreads();
        #pragma unroll
        for (int k = 0; k < 8; k++){
            float4 w = *(const float4*)&Bs[k][tx*4];
            float4 a = *(const float4*)&As[k][ty*4];
            acc[0][0] += a.x*w.x; acc[0][1] += a.x*w.y; acc[0][2] += a.x*w.z; acc[0][3] += a.x*w.w;
            acc[1][0] += a.y*w.x; acc[1][1] += a.y*w.y; acc[1][2] += a.y*w.z; acc[1][3] += a.y*w.w;
            acc[2][0] += a.z*w.x; acc[2][1] += a.z*w.y; acc[2][2] += a.z*w.z; acc[2][3] += a.z*w.w;
            acc[3][0] += a.w*w.x; acc[3][1] += a.w*w.y; acc[3][2] += a.w*w.z; acc[3][3] += a.w*w.w;
        }
        __syncthreads();
    }
    // Epilogue: add bias, scatter into gate-interleaved layout [t][b][hc*4+g]
    #pragma unroll
    for (int i = 0; i < 4; i++){
        int m  = m0 + ty*4 + i;
        int tt = m >> 8, bb = m & 255;
        #pragma unroll
        for (int j = 0; j < 4; j++){
            int col = n0 + tx*4 + j;          // 0..1023 within dir
            int g   = col >> 8;               // 0=i, 1=j, 2=f, 3=o
            int hc  = col & 255;
            d_xz[dir][tt][bb][hc*4 + g] = acc[i][j] + bg[col];
        }
    }
}

// ---------------------------------------------------------------------------
// Kernel 3: persistent bidirectional LSTM recurrence.
// 128 blocks = 2 dirs x 8 batch-tiles(32) x 8 hcol-tiles(32).
// W_h tile (256 x 128 interleaved cols) cached in smem once; c in registers.
// Grid barrier (sense reversal) between steps.
// ---------------------------------------------------------------------------
__global__ void __launch_bounds__(256, 1)
k_rnn(const float* __restrict__ Wfw, const float* __restrict__ Wbw){
    extern __shared__ float smem[];
    float (*sWh)[128] = (float(*)[128])smem;             // [256][128]
    float (*sh)[260]  = (float(*)[260])(smem + 256*128); // [32][260] (padded)

    int tid = threadIdx.x;
    int bid = blockIdx.x;
    int dir = bid >> 6;
    int tl  = bid & 63;
    int b0  = (tl >> 3) * 32;
    int h0  = (tl & 7) * 32;
    const float* __restrict__ Wg = dir ? Wbw : Wfw;

    // Load recurrent weight tile once, gate-interleaved: sWh[k][hj*4+g]
    for (int idx = tid; idx < 256*128; idx += 256){
        int k = idx >> 7, c = idx & 127;
        int hj = c >> 2, g = c & 3;
        sWh[k][c] = Wg[(EMB + k)*GATES + g*HID + h0 + hj];
    }

    int tx = tid & 31;   // hidden column hj within tile
    int ty = tid >> 5;   // batch group (4 rows each)
    int   len_i[4];
    float c_reg[4];
    #pragma unroll
    for (int i = 0; i < 4; i++){ len_i[i] = d_len[b0 + ty*4 + i]; c_reg[i] = 0.0f; }

    unsigned sense = 0;
    if (tid == 0) sense = *(volatile unsigned*)&g_bar_sense;

    for (int t = 0; t < SEQT; t++){
        int cur = t & 1, nxt = cur ^ 1;
        // Load previous h for our 32 batch rows (all 256 k)
        for (int idx = tid; idx < 32*256; idx += 256){
            int b = idx >> 8, k = idx & 255;
            sh[b][k] = d_hbuf[dir][cur][b0 + b][k];
        }
        __syncthreads();

        float acc[4][4];
        #pragma unroll
        for (int i = 0; i < 4; i++){
            acc[i][0] = 0.0f; acc[i][1] = 0.0f; acc[i][2] = 0.0f; acc[i][3] = 0.0f;
        }
        #pragma unroll 8
        for (int k = 0; k < 256; k++){
            float4 w = *(const float4*)&sWh[k][tx*4];
            #pragma unroll
            for (int i = 0; i < 4; i++){
                float a = sh[ty*4 + i][k];
                acc[i][0] += a*w.x;
                acc[i][1] += a*w.y;
                acc[i][2] += a*w.z;
                acc[i][3] += a*w.w;
            }
        }

        int teff = dir ? (SEQT - 1 - t) : t;
        #pragma unroll
        for (int i = 0; i < 4; i++){
            int bb = b0 + ty*4 + i;
            float4 xz = *(const float4*)&d_xz[dir][teff][bb][(h0 + tx)*4];
            float zi = acc[i][0] + xz.x;
            float zj = acc[i][1] + xz.y;
            float zf = acc[i][2] + xz.z;
            float zo = acc[i][3] + xz.w;
            float nc = c_reg[i]*sigf(zf + 1.0f) + sigf(zi)*tanhf(zj);
            float nh = tanhf(nc)*sigf(zo);
            float hold = sh[ty*4 + i][h0 + tx];
            bool valid = (teff < len_i[i]);
            if (valid) c_reg[i] = nc;
            d_hbuf[dir][nxt][bb][h0 + tx] = valid ? nh : hold;
        }

        // ---- grid barrier (sense reversal) ----
        __syncthreads();
        if (tid == 0){
            __threadfence();
            unsigned s = sense ^ 1;
            sense = s;
            unsigned n = atomicAdd(&g_bar_count, 1) + 1;
            if (n == NBLK){
                atomicExch(&g_bar_count, 0);
                __threadfence();
                atomicExch(&g_bar_sense, s);
            } else {
                while (*(volatile unsigned*)&g_bar_sense != s) __nanosleep(64);
            }
            __threadfence();
        }
        __syncthreads();
    }
}

// ---------------------------------------------------------------------------
// Kernel 4: final projection scores = [h_fw | h_bw] @ W_out + b_out
// ---------------------------------------------------------------------------
__global__ void k_out(const float* __restrict__ Wout, const float* __restrict__ bout,
                      float* __restrict__ out){
    int b = blockIdx.x;
    int tid = threadIdx.x;
    float s0 = 0.0f, s1 = 0.0f;
    for (int k = tid; k < 512; k += 256){
        float v = (k < 256) ? d_hbuf[0][0][b][k] : d_hbuf[1][0][b][k - 256];
        s0 += v*Wout[2*k];
        s1 += v*Wout[2*k + 1];
    }
    #pragma unroll
    for (int o = 16; o; o >>= 1){
        s0 += __shfl_down_sync(0xffffffffu, s0, o);
        s1 += __shfl_down_sync(0xffffffffu, s1, o);
    }
    __shared__ float r0[8], r1[8];
    int w = tid >> 5;
    if ((tid & 31) == 0){ r0[w] = s0; r1[w] = s1; }
    __syncthreads();
    if (tid == 0){
        float t0 = bout[0], t1 = bout[1];
        #pragma unroll
        for (int i = 0; i < 8; i++){ t0 += r0[i]; t1 += r1[i]; }
        out[2*b]     = t0;
        out[2*b + 1] = t1;
    }
}

// ---------------------------------------------------------------------------
extern "C" void kernel_launch(void* const* d_in, const int* in_sizes, int n_in,
                              void* d_out, int out_size){
    const int*   ids  = (const int*)  d_in[0];
    const float* emb  = (const float*)d_in[1];
    const float* Wfw  = (const float*)d_in[2];
    const float* bfw  = (const float*)d_in[3];
    const float* Wbw  = (const float*)d_in[4];
    const float* bbw  = (const float*)d_in[5];
    const float* Wout = (const float*)d_in[6];
    const float* bout = (const float*)d_in[7];
    float* out = (float*)d_out;

    cudaFuncSetAttribute(k_rnn, cudaFuncAttributeMaxDynamicSharedMemorySize, SMEM_RNN);

    k_init<<<BATCH, 128>>>(ids);
    dim3 g2(2048, 32);
    k_ingemm<<<g2, 256>>>(ids, emb, Wfw, bfw, Wbw, bbw);
    k_rnn<<<NBLK, 256, SMEM_RNN>>>(Wfw, Wbw);
    k_out<<<BATCH, 256>>>(Wout, bout, out);
}

// round 2
// speedup vs baseline: 1.6291x; 1.6291x over previous
#include <cuda_runtime.h>
#include <math.h>

#define BATCH 256
#define SEQT  512
#define VOCAB 50000
#define EMB   300
#define HID   256
#define GATES 1024   // 4*HID
#define NBLK  128
#define SMEM_RNN (256*128*4 + 32*260*4)   // Wh tile + h tile = 164352 B

// Scratch (static device memory — allocation-free)
__device__ float d_proj[VOCAB][2*GATES];        // [v][dir*1024 + hc*4 + g], bias folded in
__device__ float d_hbuf[2][2][BATCH][HID];      // [dir][pingpong][b][h]
__device__ int   d_len[BATCH];
__device__ unsigned g_bar_count;
__device__ unsigned g_bar_sense;

__device__ __forceinline__ float sigf(float x){ return 1.0f/(1.0f + expf(-x)); }

// ---------------------------------------------------------------------------
// Kernel 1: lengths + zero initial states
// ---------------------------------------------------------------------------
__global__ void k_init(const int* __restrict__ ids){
    int b = blockIdx.x;
    __shared__ int cnt;
    if (threadIdx.x == 0) cnt = 0;
    __syncthreads();
    int c = 0;
    for (int t = threadIdx.x; t < SEQT; t += blockDim.x)
        c += (ids[b*SEQT + t] != 0);
    #pragma unroll
    for (int o = 16; o; o >>= 1) c += __shfl_down_sync(0xffffffffu, c, o);
    if ((threadIdx.x & 31) == 0) atomicAdd(&cnt, c);
    __syncthreads();
    if (threadIdx.x == 0) d_len[b] = cnt;
    for (int i = threadIdx.x; i < HID; i += blockDim.x){
        d_hbuf[0][0][b][i] = 0.0f;
        d_hbuf[1][0][b][i] = 0.0f;
    }
}

// ---------------------------------------------------------------------------
// Kernel 2: vocab projection GEMM: proj[v] = emb[v] @ Wx + bias  (both dirs)
// M = 50000, N = 2*1024, K = 300. 128x128 tile, BK=8, 256 threads, 8x8/thread.
// Output scattered gate-interleaved: proj[v][dir*1024 + hc*4 + g].
// ---------------------------------------------------------------------------
__global__ void __launch_bounds__(256, 2)
k_vgemm(const float* __restrict__ emb,
        const float* __restrict__ Wfw, const float* __restrict__ bfw,
        const float* __restrict__ Wbw, const float* __restrict__ bbw){
    __shared__ float As[8][128];
    __shared__ float Bs[8][128];
    int m0  = blockIdx.x * 128;
    int ny  = blockIdx.y;            // 0..15
    int dir = ny >> 3;
    int n0  = (ny & 7) * 128;        // within-dir column offset
    const float* __restrict__ Wg = dir ? Wbw : Wfw;
    const float* __restrict__ bg = dir ? bbw : bfw;
    int t  = threadIdx.x;
    int tx = t & 15, ty = t >> 4;

    int a_row = t >> 1;              // 0..127
    int a_col = (t & 1) * 4;         // 0 or 4
    int b_row = t >> 5;              // 0..7
    int b_col = (t & 31) * 4;        // 0..124

    float acc[8][8] = {};
    for (int k0 = 0; k0 < EMB; k0 += 8){
        // Load A tile (transposed into smem). emb row stride 300*4=1200B (16B mult).
        float4 av = make_float4(0.f,0.f,0.f,0.f);
        int gm = m0 + a_row;
        if (gm < VOCAB && (k0 + a_col) < EMB)   // 300 % 4 == 0 -> full float4 valid
            av = *(const float4*)&emb[(size_t)gm*EMB + k0 + a_col];
        As[a_col+0][a_row] = av.x;
        As[a_col+1][a_row] = av.y;
        As[a_col+2][a_row] = av.z;
        As[a_col+3][a_row] = av.w;
        // Load B tile
        float4 bv = make_float4(0.f,0.f,0.f,0.f);
        if (k0 + b_row < EMB)
            bv = *(const float4*)&Wg[(size_t)(k0 + b_row)*GATES + n0 + b_col];
        *(float4*)&Bs[b_row][b_col] = bv;
        __syncthreads();
        #pragma unroll
        for (int k = 0; k < 8; k++){
            float4 a0 = *(const float4*)&As[k][ty*8];
            float4 a1 = *(const float4*)&As[k][ty*8 + 4];
            float4 w0 = *(const float4*)&Bs[k][tx*8];
            float4 w1 = *(const float4*)&Bs[k][tx*8 + 4];
            float a[8] = {a0.x,a0.y,a0.z,a0.w,a1.x,a1.y,a1.z,a1.w};
            float w[8] = {w0.x,w0.y,w0.z,w0.w,w1.x,w1.y,w1.z,w1.w};
            #pragma unroll
            for (int i = 0; i < 8; i++)
                #pragma unroll
                for (int j = 0; j < 8; j++)
                    acc[i][j] += a[i]*w[j];
        }
        __syncthreads();
    }
    // Epilogue: bias + scatter into gate-interleaved layout
    #pragma unroll
    for (int i = 0; i < 8; i++){
        int gm = m0 + ty*8 + i;
        if (gm >= VOCAB) continue;
        #pragma unroll
        for (int j = 0; j < 8; j++){
            int col = n0 + tx*8 + j;        // 0..1023 within dir (g*256+hc order)
            int g   = col >> 8;
            int hc  = col & 255;
            d_proj[gm][dir*GATES + hc*4 + g] = acc[i][j] + bg[col];
        }
    }
}

// ---------------------------------------------------------------------------
// Kernel 3: persistent bidirectional LSTM recurrence with fused proj gather.
// 128 blocks = 2 dirs x 8 batch-tiles(32) x 8 hcol-tiles(32).
// ---------------------------------------------------------------------------
__global__ void __launch_bounds__(256, 1)
k_rnn(const float* __restrict__ Wfw, const float* __restrict__ Wbw,
      const int* __restrict__ ids){
    extern __shared__ float smem[];
    float (*sWh)[128] = (float(*)[128])smem;             // [256][128]
    float (*sh)[260]  = (float(*)[260])(smem + 256*128); // [32][260] (padded, 16B-mult stride)
    __shared__ int s_id[32];

    int tid = threadIdx.x;
    int bid = blockIdx.x;
    int dir = bid >> 6;
    int tl  = bid & 63;
    int b0  = (tl >> 3) * 32;
    int h0  = (tl & 7) * 32;
    const float* __restrict__ Wg = dir ? Wbw : Wfw;

    // Load recurrent weight tile once, gate-interleaved: sWh[k][hj*4+g]
    for (int idx = tid; idx < 256*128; idx += 256){
        int k = idx >> 7, c = idx & 127;
        int hj = c >> 2, g = c & 3;
        sWh[k][c] = Wg[(EMB + k)*GATES + g*HID + h0 + hj];
    }

    int tx = tid & 31;   // hidden column hj within tile
    int ty = tid >> 5;   // batch group (4 rows each)
    int   len_i[4];
    float c_reg[4];
    #pragma unroll
    for (int i = 0; i < 4; i++){ len_i[i] = d_len[b0 + ty*4 + i]; c_reg[i] = 0.0f; }

    unsigned sense = 0;
    if (tid == 0) sense = *(volatile unsigned*)&g_bar_sense;

    for (int t = 0; t < SEQT; t++){
        int cur = t & 1, nxt = cur ^ 1;
        int teff = dir ? (SEQT - 1 - t) : t;
        // Load previous h tile (float4) + token ids for this step
        for (int idx = tid; idx < 32*64; idx += 256){
            int b = idx >> 6, kq = idx & 63;
            *(float4*)&sh[b][kq*4] = *(const float4*)&d_hbuf[dir][cur][b0 + b][kq*4];
        }
        if (tid < 32) s_id[tid] = ids[(b0 + tid)*SEQT + teff];
        __syncthreads();

        // Prefetch input-projection gather (hidden under the MMA loop below)
        float4 xz4[4];
        #pragma unroll
        for (int i = 0; i < 4; i++){
            int id = s_id[ty*4 + i];
            xz4[i] = *(const float4*)&d_proj[id][dir*GATES + (h0 + tx)*4];
        }

        float acc[4][4] = {};
        #pragma unroll 4
        for (int k = 0; k < 256; k += 4){
            float4 a4[4];
            #pragma unroll
            for (int i = 0; i < 4; i++)
                a4[i] = *(const float4*)&sh[ty*4 + i][k];
            #pragma unroll
            for (int kk = 0; kk < 4; kk++){
                float4 w = *(const float4*)&sWh[k + kk][tx*4];
                #pragma unroll
                for (int i = 0; i < 4; i++){
                    float a = (kk == 0) ? a4[i].x : (kk == 1) ? a4[i].y
                            : (kk == 2) ? a4[i].z : a4[i].w;
                    acc[i][0] += a*w.x;
                    acc[i][1] += a*w.y;
                    acc[i][2] += a*w.z;
                    acc[i][3] += a*w.w;
                }
            }
        }

        #pragma unroll
        for (int i = 0; i < 4; i++){
            int bb = b0 + ty*4 + i;
            float zi = acc[i][0] + xz4[i].x;
            float zj = acc[i][1] + xz4[i].y;
            float zf = acc[i][2] + xz4[i].z;
            float zo = acc[i][3] + xz4[i].w;
            float nc = c_reg[i]*sigf(zf + 1.0f) + sigf(zi)*tanhf(zj);
            float nh = tanhf(nc)*sigf(zo);
            float hold = sh[ty*4 + i][h0 + tx];
            bool valid = (teff < len_i[i]);
            if (valid) c_reg[i] = nc;
            d_hbuf[dir][nxt][bb][h0 + tx] = valid ? nh : hold;
        }

        // ---- grid barrier (sense reversal) ----
        __syncthreads();
        if (tid == 0){
            __threadfence();
            unsigned s = sense ^ 1;
            sense = s;
            unsigned n = atomicAdd(&g_bar_count, 1) + 1;
            if (n == NBLK){
                atomicExch(&g_bar_count, 0);
                __threadfence();
                atomicExch(&g_bar_sense, s);
            } else {
                while (*(volatile unsigned*)&g_bar_sense != s) __nanosleep(64);
            }
            __threadfence();
        }
        __syncthreads();
    }
}

// ---------------------------------------------------------------------------
// Kernel 4: final projection scores = [h_fw | h_bw] @ W_out + b_out
// ---------------------------------------------------------------------------
__global__ void k_out(const float* __restrict__ Wout, const float* __restrict__ bout,
                      float* __restrict__ out){
    int b = blockIdx.x;
    int tid = threadIdx.x;
    float s0 = 0.0f, s1 = 0.0f;
    for (int k = tid; k < 512; k += 256){
        float v = (k < 256) ? d_hbuf[0][0][b][k] : d_hbuf[1][0][b][k - 256];
        s0 += v*Wout[2*k];
        s1 += v*Wout[2*k + 1];
    }
    #pragma unroll
    for (int o = 16; o; o >>= 1){
        s0 += __shfl_down_sync(0xffffffffu, s0, o);
        s1 += __shfl_down_sync(0xffffffffu, s1, o);
    }
    __shared__ float r0[8], r1[8];
    int w = tid >> 5;
    if ((tid & 31) == 0){ r0[w] = s0; r1[w] = s1; }
    __syncthreads();
    if (tid == 0){
        float t0 = bout[0], t1 = bout[1];
        #pragma unroll
        for (int i = 0; i < 8; i++){ t0 += r0[i]; t1 += r1[i]; }
        out[2*b]     = t0;
        out[2*b + 1] = t1;
    }
}

// ---------------------------------------------------------------------------
extern "C" void kernel_launch(void* const* d_in, const int* in_sizes, int n_in,
                              void* d_out, int out_size){
    const int*   ids  = (const int*)  d_in[0];
    const float* emb  = (const float*)d_in[1];
    const float* Wfw  = (const float*)d_in[2];
    const float* bfw  = (const float*)d_in[3];
    const float* Wbw  = (const float*)d_in[4];
    const float* bbw  = (const float*)d_in[5];
    const float* Wout = (const float*)d_in[6];
    const float* bout = (const float*)d_in[7];
    float* out = (float*)d_out;

    cudaFuncSetAttribute(k_rnn, cudaFuncAttributeMaxDynamicSharedMemorySize, SMEM_RNN);

    k_init<<<BATCH, 128>>>(ids);
    dim3 g2((VOCAB + 127)/128, 16);
    k_vgemm<<<g2, 256>>>(emb, Wfw, bfw, Wbw, bbw);
    k_rnn<<<NBLK, 256, SMEM_RNN>>>(Wfw, Wbw, ids);
    k_out<<<BATCH, 256>>>(Wout, bout, out);
}

// round 3
// speedup vs baseline: 2.0721x; 1.2720x over previous
#include <cuda_runtime.h>
#include <math.h>

#define BATCH 256
#define SEQT  512
#define VOCAB 50000
#define EMB   300
#define HID   256
#define GATES 1024   // 4*HID
#define NBLK  128
// sWb (32768 u32) + sh2 (32*264 u32)
#define SMEM_RNN (32768*4 + 32*264*4)

// Scratch (static device memory — allocation-free)
__device__ float d_proj[VOCAB][2*GATES];        // [v][dir*1024 + hc*4 + g], bias folded in
__device__ float d_hbuf[2][2][BATCH][HID];      // [dir][pingpong][b][h]
__device__ int   d_len[BATCH];
__device__ unsigned g_bar_count;
__device__ unsigned g_bar_sense;

__device__ __forceinline__ float sigf(float x){ return 1.0f/(1.0f + expf(-x)); }
__device__ __forceinline__ unsigned f2tf(float v){
    unsigned u; asm("cvt.rna.tf32.f32 %0, %1;" : "=r"(u) : "f"(v)); return u;
}
// k-permutation so that (c, c+4) land adjacent -> A fragment via one LDS.64
__device__ __forceinline__ int kperm(int k){
    return (k & ~7) + (k & 3)*2 + ((k >> 2) & 1);
}

// ---------------------------------------------------------------------------
// Kernel 1: lengths + zero initial states
// ---------------------------------------------------------------------------
__global__ void k_init(const int* __restrict__ ids){
    int b = blockIdx.x;
    __shared__ int cnt;
    if (threadIdx.x == 0) cnt = 0;
    __syncthreads();
    int c = 0;
    for (int t = threadIdx.x; t < SEQT; t += blockDim.x)
        c += (ids[b*SEQT + t] != 0);
    #pragma unroll
    for (int o = 16; o; o >>= 1) c += __shfl_down_sync(0xffffffffu, c, o);
    if ((threadIdx.x & 31) == 0) atomicAdd(&cnt, c);
    __syncthreads();
    if (threadIdx.x == 0) d_len[b] = cnt;
    for (int i = threadIdx.x; i < HID; i += blockDim.x){
        d_hbuf[0][0][b][i] = 0.0f;
        d_hbuf[1][0][b][i] = 0.0f;
    }
}

// ---------------------------------------------------------------------------
// Kernel 2: vocab projection GEMM: proj[v] = emb[v] @ Wx + bias  (both dirs)
// ---------------------------------------------------------------------------
__global__ void __launch_bounds__(256, 2)
k_vgemm(const float* __restrict__ emb,
        const float* __restrict__ Wfw, const float* __restrict__ bfw,
        const float* __restrict__ Wbw, const float* __restrict__ bbw){
    __shared__ float As[8][128];
    __shared__ float Bs[8][128];
    int m0  = blockIdx.x * 128;
    int ny  = blockIdx.y;            // 0..15
    int dir = ny >> 3;
    int n0  = (ny & 7) * 128;
    const float* __restrict__ Wg = dir ? Wbw : Wfw;
    const float* __restrict__ bg = dir ? bbw : bfw;
    int t  = threadIdx.x;
    int tx = t & 15, ty = t >> 4;

    int a_row = t >> 1;
    int a_col = (t & 1) * 4;
    int b_row = t >> 5;
    int b_col = (t & 31) * 4;

    float acc[8][8] = {};
    for (int k0 = 0; k0 < EMB; k0 += 8){
        float4 av = make_float4(0.f,0.f,0.f,0.f);
        int gm = m0 + a_row;
        if (gm < VOCAB && (k0 + a_col) < EMB)
            av = *(const float4*)&emb[(size_t)gm*EMB + k0 + a_col];
        As[a_col+0][a_row] = av.x;
        As[a_col+1][a_row] = av.y;
        As[a_col+2][a_row] = av.z;
        As[a_col+3][a_row] = av.w;
        float4 bv = make_float4(0.f,0.f,0.f,0.f);
        if (k0 + b_row < EMB)
            bv = *(const float4*)&Wg[(size_t)(k0 + b_row)*GATES + n0 + b_col];
        *(float4*)&Bs[b_row][b_col] = bv;
        __syncthreads();
        #pragma unroll
        for (int k = 0; k < 8; k++){
            float4 a0 = *(const float4*)&As[k][ty*8];
            float4 a1 = *(const float4*)&As[k][ty*8 + 4];
            float4 w0 = *(const float4*)&Bs[k][tx*8];
            float4 w1 = *(const float4*)&Bs[k][tx*8 + 4];
            float a[8] = {a0.x,a0.y,a0.z,a0.w,a1.x,a1.y,a1.z,a1.w};
            float w[8] = {w0.x,w0.y,w0.z,w0.w,w1.x,w1.y,w1.z,w1.w};
            #pragma unroll
            for (int i = 0; i < 8; i++)
                #pragma unroll
                for (int j = 0; j < 8; j++)
                    acc[i][j] += a[i]*w[j];
        }
        __syncthreads();
    }
    #pragma unroll
    for (int i = 0; i < 8; i++){
        int gm = m0 + ty*8 + i;
        if (gm >= VOCAB) continue;
        #pragma unroll
        for (int j = 0; j < 8; j++){
            int col = n0 + tx*8 + j;
            int g   = col >> 8;
            int hc  = col & 255;
            d_proj[gm][dir*GATES + hc*4 + g] = acc[i][j] + bg[col];
        }
    }
}

// ---------------------------------------------------------------------------
// Kernel 3: persistent bidirectional LSTM recurrence — tf32 tensor cores.
// 128 blocks = 2 dirs x 8 batch-tiles(32) x 8 hcol-tiles(32).
// Per block/step: Z[32 x (4 gates x 32 hid)] = H[32x256] @ Wh-tile, via
// mma.sync.m16n8k8.tf32. 8 warps = 2 batch halves x 4 hid groups of 8.
// Each warp holds 4 gate accumulators with identical (b,hj) lane mapping.
// ---------------------------------------------------------------------------
__global__ void __launch_bounds__(256, 1)
k_rnn(const float* __restrict__ Wfw, const float* __restrict__ Wbw,
      const int* __restrict__ ids){
    extern __shared__ unsigned smem_u[];
    unsigned* sWb = smem_u;            // [4 gates][4 wg][32 kb][64] fragment-ordered tf32
    unsigned* sh2 = smem_u + 32768;    // [32][264] k-permuted tf32 h
    __shared__ int s_id[32];

    int tid = threadIdx.x;
    int bid = blockIdx.x;
    int dir = bid >> 6;
    int tl  = bid & 63;
    int b0  = (tl >> 3) * 32;
    int h0  = (tl & 7) * 32;
    const float* __restrict__ Wg = dir ? Wbw : Wfw;

    int lane = tid & 31;
    int w    = tid >> 5;
    int mr   = w & 1;       // batch half
    int wg   = w >> 1;      // hid group of 8
    int gid  = lane >> 2;
    int qq   = lane & 3;

    // ---- Fill Wh fragments once (tf32) ----
    // sWb flat f = g*8192 + wg*2048 + kb*64 + lane*2 + s
    // meaning: B frag b_s for (k = kb*8 + (lane&3) + s*4, n = lane>>2)
    for (int f = tid; f < 32768; f += 256){
        int s   = f & 1;
        int ln  = (f >> 1) & 31;
        int kb  = (f >> 6) & 31;
        int wgf = (f >> 11) & 3;
        int g   = (f >> 13) & 3;
        int k   = kb*8 + (ln & 3) + s*4;
        int col = g*HID + h0 + wgf*8 + (ln >> 2);
        sWb[f] = f2tf(Wg[(EMB + k)*GATES + col]);
    }

    int rb0 = mr*16 + gid;      // block-local batch rows this thread owns
    int rb1 = rb0 + 8;
    int hc0 = wg*8 + qq*2;      // block-local hidden cols (hc0, hc0+1)
    int len0 = d_len[b0 + rb0];
    int len1 = d_len[b0 + rb1];
    float c_reg[4] = {0.f, 0.f, 0.f, 0.f};   // [rr*2+cc]

    unsigned sense = 0;
    if (tid == 0) sense = *(volatile unsigned*)&g_bar_sense;

    for (int t = 0; t < SEQT; t++){
        int cur = t & 1, nxt = cur ^ 1;
        int teff = dir ? (SEQT - 1 - t) : t;

        // stage h (tf32, k-permuted) + token ids
        for (int idx = tid; idx < 32*256; idx += 256){
            int b = idx >> 8, k = idx & 255;
            sh2[b*264 + kperm(k)] = f2tf(d_hbuf[dir][cur][b0 + b][k]);
        }
        if (tid < 32) s_id[tid] = ids[(b0 + tid)*SEQT + teff];
        __syncthreads();

        // prefetch input-projection gathers (hidden under the MMA loop)
        float4 xz[2][2];
        {
            int id0 = s_id[rb0], id1 = s_id[rb1];
            const float* p0 = &d_proj[id0][dir*GATES];
            const float* p1 = &d_proj[id1][dir*GATES];
            xz[0][0] = *(const float4*)&p0[(h0 + hc0    )*4];
            xz[0][1] = *(const float4*)&p0[(h0 + hc0 + 1)*4];
            xz[1][0] = *(const float4*)&p1[(h0 + hc0    )*4];
            xz[1][1] = *(const float4*)&p1[(h0 + hc0 + 1)*4];
        }

        float acc[4][4];
        #pragma unroll
        for (int g = 0; g < 4; g++){
            acc[g][0]=0.f; acc[g][1]=0.f; acc[g][2]=0.f; acc[g][3]=0.f;
        }

        #pragma unroll 4
        for (int kb = 0; kb < 32; kb++){
            uint2 aA = *(const uint2*)&sh2[rb0*264 + kb*8 + qq*2]; // (a0,a2)
            uint2 aB = *(const uint2*)&sh2[rb1*264 + kb*8 + qq*2]; // (a1,a3)
            #pragma unroll
            for (int g = 0; g < 4; g++){
                uint2 bb = *(const uint2*)&sWb[g*8192 + wg*2048 + kb*64 + lane*2];
                asm volatile(
                    "mma.sync.aligned.m16n8k8.row.col.f32.tf32.tf32.f32 "
                    "{%0,%1,%2,%3},{%4,%5,%6,%7},{%8,%9},{%0,%1,%2,%3};"
                    : "+f"(acc[g][0]), "+f"(acc[g][1]), "+f"(acc[g][2]), "+f"(acc[g][3])
                    : "r"(aA.x), "r"(aB.x), "r"(aA.y), "r"(aB.y),
                      "r"(bb.x), "r"(bb.y));
            }
        }

        // elementwise LSTM cell on the 4 (b,hj) cells this thread owns
        #pragma unroll
        for (int rr = 0; rr < 2; rr++){
            int bl  = rr ? rb1 : rb0;
            int len = rr ? len1 : len0;
            bool valid = (teff < len);
            #pragma unroll
            for (int cc = 0; cc < 2; cc++){
                int hj = hc0 + cc;
                int ci = rr*2 + cc;
                float zi = acc[0][ci] + xz[rr][cc].x;
                float zj = acc[1][ci] + xz[rr][cc].y;
                float zf = acc[2][ci] + xz[rr][cc].z;
                float zo = acc[3][ci] + xz[rr][cc].w;
                float nc = c_reg[ci]*sigf(zf + 1.0f) + sigf(zi)*tanhf(zj);
                float nh = tanhf(nc)*sigf(zo);
                float hold = __uint_as_float(sh2[bl*264 + kperm(h0 + hj)]);
                if (valid) c_reg[ci] = nc;
                d_hbuf[dir][nxt][b0 + bl][h0 + hj] = valid ? nh : hold;
            }
        }

        // ---- grid barrier (sense reversal) ----
        __syncthreads();
        if (tid == 0){
            __threadfence();
            unsigned s = sense ^ 1;
            sense = s;
            unsigned n = atomicAdd(&g_bar_count, 1) + 1;
            if (n == NBLK){
                atomicExch(&g_bar_count, 0);
                __threadfence();
                atomicExch(&g_bar_sense, s);
            } else {
                while (*(volatile unsigned*)&g_bar_sense != s) __nanosleep(64);
            }
            __threadfence();
        }
        __syncthreads();
    }
}

// ---------------------------------------------------------------------------
// Kernel 4: final projection scores = [h_fw | h_bw] @ W_out + b_out
// ---------------------------------------------------------------------------
__global__ void k_out(const float* __restrict__ Wout, const float* __restrict__ bout,
                      float* __restrict__ out){
    int b = blockIdx.x;
    int tid = threadIdx.x;
    float s0 = 0.0f, s1 = 0.0f;
    for (int k = tid; k < 512; k += 256){
        float v = (k < 256) ? d_hbuf[0][0][b][k] : d_hbuf[1][0][b][k - 256];
        s0 += v*Wout[2*k];
        s1 += v*Wout[2*k + 1];
    }
    #pragma unroll
    for (int o = 16; o; o >>= 1){
        s0 += __shfl_down_sync(0xffffffffu, s0, o);
        s1 += __shfl_down_sync(0xffffffffu, s1, o);
    }
    __shared__ float r0[8], r1[8];
    int w = tid >> 5;
    if ((tid & 31) == 0){ r0[w] = s0; r1[w] = s1; }
    __syncthreads();
    if (tid == 0){
        float t0 = bout[0], t1 = bout[1];
        #pragma unroll
        for (int i = 0; i < 8; i++){ t0 += r0[i]; t1 += r1[i]; }
        out[2*b]     = t0;
        out[2*b + 1] = t1;
    }
}

// ---------------------------------------------------------------------------
extern "C" void kernel_launch(void* const* d_in, const int* in_sizes, int n_in,
                              void* d_out, int out_size){
    const int*   ids  = (const int*)  d_in[0];
    const float* emb  = (const float*)d_in[1];
    const float* Wfw  = (const float*)d_in[2];
    const float* bfw  = (const float*)d_in[3];
    const float* Wbw  = (const float*)d_in[4];
    const float* bbw  = (const float*)d_in[5];
    const float* Wout = (const float*)d_in[6];
    const float* bout = (const float*)d_in[7];
    float* out = (float*)d_out;

    cudaFuncSetAttribute(k_rnn, cudaFuncAttributeMaxDynamicSharedMemorySize, SMEM_RNN);

    k_init<<<BATCH, 128>>>(ids);
    dim3 g2((VOCAB + 127)/128, 16);
    k_vgemm<<<g2, 256>>>(emb, Wfw, bfw, Wbw, bbw);
    k_rnn<<<NBLK, 256, SMEM_RNN>>>(Wfw, Wbw, ids);
    k_out<<<BATCH, 256>>>(Wout, bout, out);
}

// round 4
// speedup vs baseline: 3.3044x; 1.5947x over previous
#include <cuda_runtime.h>
#include <math.h>

#define BATCH 256
#define SEQT  512
#define VOCAB 50000
#define EMB   300
#define HID   256
#define GATES 1024   // 4*HID
#define NBLK  128
// sWb (32768 u32) + sh2 (32*264 u32)
#define SMEM_RNN (32768*4 + 32*264*4)

// Scratch (static device memory — allocation-free)
__device__ float    d_proj[VOCAB][2*GATES];      // [v][dir*1024 + hc*4 + g], bias folded in
__device__ unsigned d_hbuf[2][2][BATCH][264];    // tf32, k-permuted layout (matches sh2)
__device__ float    d_hfinal[2][BATCH][HID];     // fp32 final hidden state
__device__ int      d_len[BATCH];
__device__ unsigned g_bar_count[2];
__device__ unsigned g_bar_sense[2];

__device__ __forceinline__ float sigf(float x){ return 1.0f/(1.0f + expf(-x)); }
__device__ __forceinline__ unsigned f2tf(float v){
    unsigned u; asm("cvt.rna.tf32.f32 %0, %1;" : "=r"(u) : "f"(v)); return u;
}
// k-permutation so that (c, c+4) land adjacent -> A fragment via one LDS.64
__device__ __forceinline__ int kperm(int k){
    return (k & ~7) + (k & 3)*2 + ((k >> 2) & 1);
}

// ---------------------------------------------------------------------------
// Kernel 1: lengths + zero initial (permuted-tf32) h states
// ---------------------------------------------------------------------------
__global__ void k_init(const int* __restrict__ ids){
    int b = blockIdx.x;
    __shared__ int cnt;
    if (threadIdx.x == 0) cnt = 0;
    __syncthreads();
    int c = 0;
    for (int t = threadIdx.x; t < SEQT; t += blockDim.x)
        c += (ids[b*SEQT + t] != 0);
    #pragma unroll
    for (int o = 16; o; o >>= 1) c += __shfl_down_sync(0xffffffffu, c, o);
    if ((threadIdx.x & 31) == 0) atomicAdd(&cnt, c);
    __syncthreads();
    if (threadIdx.x == 0) d_len[b] = cnt;
    for (int i = threadIdx.x; i < 264; i += blockDim.x){
        d_hbuf[0][0][b][i] = 0u;
        d_hbuf[0][1][b][i] = 0u;
        d_hbuf[1][0][b][i] = 0u;
        d_hbuf[1][1][b][i] = 0u;
    }
}

// ---------------------------------------------------------------------------
// Kernel 2: vocab projection GEMM via tf32 mma: proj[v] = emb[v] @ Wx + bias.
// M=50000, N=2*1024, K=300 (padded 304). Block tile 128x128, BK=16,
// 256 threads = 8 warps (2 m-halves x 4 n-quarters), warp tile 64x32.
// ---------------------------------------------------------------------------
__global__ void __launch_bounds__(256, 2)
k_vgemm(const float* __restrict__ emb,
        const float* __restrict__ Wfw, const float* __restrict__ bfw,
        const float* __restrict__ Wbw, const float* __restrict__ bbw){
    __shared__ unsigned As[16][132];   // [k][m] tf32
    __shared__ unsigned Bs[16][132];   // [k][n] tf32
    int nx  = blockIdx.x;              // 0..15 (column tiles; adjacent blocks share emb via L2)
    int dir = nx >> 3;
    int n0  = (nx & 7) * 128;
    int m0  = blockIdx.y * 128;
    const float* __restrict__ Wg = dir ? Wbw : Wfw;
    const float* __restrict__ bg = dir ? bbw : bfw;

    int t    = threadIdx.x;
    int lane = t & 31;
    int w    = t >> 5;
    int wm   = w & 1;      // m half (64)
    int wn   = w >> 1;     // n quarter (32)

    float acc[4][4][4] = {};   // [mi][ni][c0..c3]

    for (int k0 = 0; k0 < 304; k0 += 16){
        // --- load A tile: 128 rows x 16 k, as float4 along k ---
        {
            int kk = (t & 3) * 4;
            #pragma unroll
            for (int i = 0; i < 2; i++){
                int m  = (t >> 2) + i*64;
                int gm = m0 + m;
                float4 v = make_float4(0.f,0.f,0.f,0.f);
                if (gm < VOCAB && (k0 + kk + 4) <= EMB)
                    v = *(const float4*)&emb[(size_t)gm*EMB + k0 + kk];
                As[kk+0][m] = f2tf(v.x);
                As[kk+1][m] = f2tf(v.y);
                As[kk+2][m] = f2tf(v.z);
                As[kk+3][m] = f2tf(v.w);
            }
        }
        // --- load B tile: 16 k x 128 n ---
        {
            int kk = t >> 4;          // 0..15
            int nn = (t & 15) * 8;    // 0..120
            float4 v0 = make_float4(0.f,0.f,0.f,0.f);
            float4 v1 = make_float4(0.f,0.f,0.f,0.f);
            if (k0 + kk < EMB){
                v0 = *(const float4*)&Wg[(size_t)(k0 + kk)*GATES + n0 + nn];
                v1 = *(const float4*)&Wg[(size_t)(k0 + kk)*GATES + n0 + nn + 4];
            }
            Bs[kk][nn+0] = f2tf(v0.x); Bs[kk][nn+1] = f2tf(v0.y);
            Bs[kk][nn+2] = f2tf(v0.z); Bs[kk][nn+3] = f2tf(v0.w);
            Bs[kk][nn+4] = f2tf(v1.x); Bs[kk][nn+5] = f2tf(v1.y);
            Bs[kk][nn+6] = f2tf(v1.z); Bs[kk][nn+7] = f2tf(v1.w);
        }
        __syncthreads();

        #pragma unroll
        for (int k8 = 0; k8 < 2; k8++){
            int k = k8*8 + (lane & 3);
            unsigned a[4][4], b[4][2];
            #pragma unroll
            for (int mi = 0; mi < 4; mi++){
                int row = wm*64 + mi*16 + (lane >> 2);
                a[mi][0] = As[k  ][row];
                a[mi][1] = As[k  ][row + 8];
                a[mi][2] = As[k+4][row];
                a[mi][3] = As[k+4][row + 8];
            }
            #pragma unroll
            for (int ni = 0; ni < 4; ni++){
                int n = wn*32 + ni*8 + (lane >> 2);
                b[ni][0] = Bs[k  ][n];
                b[ni][1] = Bs[k+4][n];
            }
            #pragma unroll
            for (int mi = 0; mi < 4; mi++)
                #pragma unroll
                for (int ni = 0; ni < 4; ni++)
                    asm volatile(
                        "mma.sync.aligned.m16n8k8.row.col.f32.tf32.tf32.f32 "
                        "{%0,%1,%2,%3},{%4,%5,%6,%7},{%8,%9},{%0,%1,%2,%3};"
                        : "+f"(acc[mi][ni][0]), "+f"(acc[mi][ni][1]),
                          "+f"(acc[mi][ni][2]), "+f"(acc[mi][ni][3])
                        : "r"(a[mi][0]), "r"(a[mi][1]), "r"(a[mi][2]), "r"(a[mi][3]),
                          "r"(b[ni][0]), "r"(b[ni][1]));
        }
        __syncthreads();
    }

    // Epilogue: bias + gate-interleaved scatter
    #pragma unroll
    for (int mi = 0; mi < 4; mi++){
        int rbase = m0 + wm*64 + mi*16 + (lane >> 2);
        #pragma unroll
        for (int ni = 0; ni < 4; ni++){
            int cbase = n0 + wn*32 + ni*8 + (lane & 3)*2;
            #pragma unroll
            for (int c = 0; c < 4; c++){
                int gm  = rbase + (c >> 1)*8;
                int col = cbase + (c & 1);
                if (gm >= VOCAB) continue;
                int g  = col >> 8;
                int hc = col & 255;
                d_proj[gm][dir*GATES + hc*4 + g] = acc[mi][ni][c] + bg[col];
            }
        }
    }
}

// ---------------------------------------------------------------------------
// Kernel 3: persistent bidirectional LSTM recurrence — tf32 tensor cores.
// h exchange buffer is already tf32 + k-permuted in global, so staging is a
// pure vectorized copy. Per-direction grid barrier (64 blocks each).
// ---------------------------------------------------------------------------
__global__ void __launch_bounds__(256, 1)
k_rnn(const float* __restrict__ Wfw, const float* __restrict__ Wbw,
      const int* __restrict__ ids){
    extern __shared__ unsigned smem_u[];
    unsigned* sWb = smem_u;            // [4 gates][4 wg][32 kb][64] fragment-ordered tf32
    unsigned* sh2 = smem_u + 32768;    // [32][264] k-permuted tf32 h
    __shared__ int s_id[32];

    int tid = threadIdx.x;
    int bid = blockIdx.x;
    int dir = bid >> 6;
    int tl  = bid & 63;
    int b0  = (tl >> 3) * 32;
    int h0  = (tl & 7) * 32;
    const float* __restrict__ Wg = dir ? Wbw : Wfw;

    int lane = tid & 31;
    int w    = tid >> 5;
    int mr   = w & 1;       // batch half
    int wg   = w >> 1;      // hid group of 8
    int gid  = lane >> 2;
    int qq   = lane & 3;

    // ---- Fill Wh fragments once (tf32) ----
    for (int f = tid; f < 32768; f += 256){
        int s   = f & 1;
        int ln  = (f >> 1) & 31;
        int kb  = (f >> 6) & 31;
        int wgf = (f >> 11) & 3;
        int g   = (f >> 13) & 3;
        int k   = kb*8 + (ln & 3) + s*4;
        int col = g*HID + h0 + wgf*8 + (ln >> 2);
        sWb[f] = f2tf(Wg[(EMB + k)*GATES + col]);
    }

    int rb0 = mr*16 + gid;      // block-local batch rows this thread owns
    int rb1 = rb0 + 8;
    int hc0 = wg*8 + qq*2;      // block-local hidden cols (hc0, hc0+1)
    int len0 = d_len[b0 + rb0];
    int len1 = d_len[b0 + rb1];
    float c_reg[4] = {0.f, 0.f, 0.f, 0.f};   // [rr*2+cc]
    float h_reg[4] = {0.f, 0.f, 0.f, 0.f};

    unsigned sense = 0;
    if (tid == 0) sense = *(volatile unsigned*)&g_bar_sense[dir];

    for (int t = 0; t < SEQT; t++){
        int cur = t & 1, nxt = cur ^ 1;
        int teff = dir ? (SEQT - 1 - t) : t;

        // token ids first (LDG latency overlaps the copy below)
        if (tid < 32) s_id[tid] = ids[(b0 + tid)*SEQT + teff];
        // stage h: pure vectorized copy (already tf32 + permuted)
        for (int idx = tid; idx < 32*66; idx += 256){
            int b = idx / 66, q = idx % 66;
            *(uint4*)&sh2[b*264 + q*4] =
                *(const uint4*)&d_hbuf[dir][cur][b0 + b][q*4];
        }
        __syncthreads();

        // prefetch input-projection gathers (hidden under the MMA loop)
        float4 xz[2][2];
        {
            int id0 = s_id[rb0], id1 = s_id[rb1];
            const float* p0 = &d_proj[id0][dir*GATES];
            const float* p1 = &d_proj[id1][dir*GATES];
            xz[0][0] = *(const float4*)&p0[(h0 + hc0    )*4];
            xz[0][1] = *(const float4*)&p0[(h0 + hc0 + 1)*4];
            xz[1][0] = *(const float4*)&p1[(h0 + hc0    )*4];
            xz[1][1] = *(const float4*)&p1[(h0 + hc0 + 1)*4];
        }

        float acc[4][4];
        #pragma unroll
        for (int g = 0; g < 4; g++){
            acc[g][0]=0.f; acc[g][1]=0.f; acc[g][2]=0.f; acc[g][3]=0.f;
        }

        #pragma unroll 4
        for (int kb = 0; kb < 32; kb++){
            uint2 aA = *(const uint2*)&sh2[rb0*264 + kb*8 + qq*2]; // (a0,a2)
            uint2 aB = *(const uint2*)&sh2[rb1*264 + kb*8 + qq*2]; // (a1,a3)
            #pragma unroll
            for (int g = 0; g < 4; g++){
                uint2 bb = *(const uint2*)&sWb[g*8192 + wg*2048 + kb*64 + lane*2];
                asm volatile(
                    "mma.sync.aligned.m16n8k8.row.col.f32.tf32.tf32.f32 "
                    "{%0,%1,%2,%3},{%4,%5,%6,%7},{%8,%9},{%0,%1,%2,%3};"
                    : "+f"(acc[g][0]), "+f"(acc[g][1]), "+f"(acc[g][2]), "+f"(acc[g][3])
                    : "r"(aA.x), "r"(aB.x), "r"(aA.y), "r"(aB.y),
                      "r"(bb.x), "r"(bb.y));
            }
        }

        // elementwise LSTM cell on the 4 (b,hj) cells this thread owns
        #pragma unroll
        for (int rr = 0; rr < 2; rr++){
            int bl  = rr ? rb1 : rb0;
            int len = rr ? len1 : len0;
            bool valid = (teff < len);
            #pragma unroll
            for (int cc = 0; cc < 2; cc++){
                int hj = hc0 + cc;
                int ci = rr*2 + cc;
                float zi = acc[0][ci] + xz[rr][cc].x;
                float zj = acc[1][ci] + xz[rr][cc].y;
                float zf = acc[2][ci] + xz[rr][cc].z;
                float zo = acc[3][ci] + xz[rr][cc].w;
                float nc = c_reg[ci]*sigf(zf + 1.0f) + sigf(zi)*tanhf(zj);
                float nh = tanhf(nc)*sigf(zo);
                if (valid){ c_reg[ci] = nc; h_reg[ci] = nh; }
                d_hbuf[dir][nxt][b0 + bl][kperm(h0 + hj)] = f2tf(h_reg[ci]);
            }
        }

        // ---- per-direction grid barrier (sense reversal) ----
        __syncthreads();
        if (tid == 0){
            __threadfence();
            unsigned s = sense ^ 1;
            sense = s;
            unsigned n = atomicAdd(&g_bar_count[dir], 1) + 1;
            if (n == 64){
                g_bar_count[dir] = 0;
                __threadfence();
                atomicExch(&g_bar_sense[dir], s);
            } else {
                while (*(volatile unsigned*)&g_bar_sense[dir] != s){}
            }
        }
        __syncthreads();
    }

    // write fp32 final hidden state
    #pragma unroll
    for (int rr = 0; rr < 2; rr++){
        int bl = rr ? rb1 : rb0;
        #pragma unroll
        for (int cc = 0; cc < 2; cc++)
            d_hfinal[dir][b0 + bl][h0 + hc0 + cc] = h_reg[rr*2 + cc];
    }
}

// ---------------------------------------------------------------------------
// Kernel 4: final projection scores = [h_fw | h_bw] @ W_out + b_out
// ---------------------------------------------------------------------------
__global__ void k_out(const float* __restrict__ Wout, const float* __restrict__ bout,
                      float* __restrict__ out){
    int b = blockIdx.x;
    int tid = threadIdx.x;
    float s0 = 0.0f, s1 = 0.0f;
    for (int k = tid; k < 512; k += 256){
        float v = (k < 256) ? d_hfinal[0][b][k] : d_hfinal[1][b][k - 256];
        s0 += v*Wout[2*k];
        s1 += v*Wout[2*k + 1];
    }
    #pragma unroll
    for (int o = 16; o; o >>= 1){
        s0 += __shfl_down_sync(0xffffffffu, s0, o);
        s1 += __shfl_down_sync(0xffffffffu, s1, o);
    }
    __shared__ float r0[8], r1[8];
    int w = tid >> 5;
    if ((tid & 31) == 0){ r0[w] = s0; r1[w] = s1; }
    __syncthreads();
    if (tid == 0){
        float t0 = bout[0], t1 = bout[1];
        #pragma unroll
        for (int i = 0; i < 8; i++){ t0 += r0[i]; t1 += r1[i]; }
        out[2*b]     = t0;
        out[2*b + 1] = t1;
    }
}

// ---------------------------------------------------------------------------
extern "C" void kernel_launch(void* const* d_in, const int* in_sizes, int n_in,
                              void* d_out, int out_size){
    const int*   ids  = (const int*)  d_in[0];
    const float* emb  = (const float*)d_in[1];
    const float* Wfw  = (const float*)d_in[2];
    const float* bfw  = (const float*)d_in[3];
    const float* Wbw  = (const float*)d_in[4];
    const float* bbw  = (const float*)d_in[5];
    const float* Wout = (const float*)d_in[6];
    const float* bout = (const float*)d_in[7];
    float* out = (float*)d_out;

    cudaFuncSetAttribute(k_rnn, cudaFuncAttributeMaxDynamicSharedMemorySize, SMEM_RNN);

    k_init<<<BATCH, 128>>>(ids);
    dim3 g2(16, (VOCAB + 127)/128);
    k_vgemm<<<g2, 256>>>(emb, Wfw, bfw, Wbw, bbw);
    k_rnn<<<NBLK, 256, SMEM_RNN>>>(Wfw, Wbw, ids);
    k_out<<<BATCH, 256>>>(Wout, bout, out);
}

// round 5
// speedup vs baseline: 3.9334x; 1.1904x over previous
#include <cuda_runtime.h>
#include <cuda_fp16.h>
#include <math.h>

#define BATCH 256
#define SEQT  512
#define VOCAB 50000
#define EMB   300
#define HID   256
#define GATES 1024   // 4*HID
#define NBLK  128
// sWb (16384 u32 = 64KB fp16 frags) + sh2 (32*132 u32 fp16 pairs)
#define SMEM_RNN (16384*4 + 32*132*4)

// Scratch (static device memory — allocation-free)
__device__ float    d_proj[VOCAB][2*GATES];      // [v][dir*1024 + hc*4 + g], bias folded in
__device__ unsigned d_hbuf[2][2][BATCH][132];    // fp16 pairs, k-permuted (matches sh2)
__device__ float    d_hfinal[2][BATCH][HID];     // fp32 final hidden state
__device__ int      d_len[BATCH];

__device__ __forceinline__ unsigned f2tf(float v){
    unsigned u; asm("cvt.rna.tf32.f32 %0, %1;" : "=r"(u) : "f"(v)); return u;
}
__device__ __forceinline__ float rcpa(float x){
    float y; asm("rcp.approx.f32 %0, %1;" : "=f"(y) : "f"(x)); return y;
}
__device__ __forceinline__ float sigf(float x){ return rcpa(1.0f + __expf(-x)); }
__device__ __forceinline__ float tanhfast(float x){
    return 1.0f - 2.0f*rcpa(1.0f + __expf(2.0f*x));
}
// pair-permutation inside a 16-k block: pair j -> slot (j&3)*2 + (j>>2)
// so thread qq reads slots (2qq, 2qq+1) = pairs (qq, qq+4) = k {2qq,2qq+1} and {2qq+8,2qq+9}
__device__ __forceinline__ int hslot(int k){   // k even; returns u32 index
    int blk = k >> 4, j = (k & 15) >> 1;
    return blk*8 + (j & 3)*2 + (j >> 2);
}

// ---------------------------------------------------------------------------
// Kernel 1: lengths + zero initial (permuted-fp16) h states
// ---------------------------------------------------------------------------
__global__ void k_init(const int* __restrict__ ids){
    int b = blockIdx.x;
    __shared__ int cnt;
    if (threadIdx.x == 0) cnt = 0;
    __syncthreads();
    int c = 0;
    for (int t = threadIdx.x; t < SEQT; t += blockDim.x)
        c += (ids[b*SEQT + t] != 0);
    #pragma unroll
    for (int o = 16; o; o >>= 1) c += __shfl_down_sync(0xffffffffu, c, o);
    if ((threadIdx.x & 31) == 0) atomicAdd(&cnt, c);
    __syncthreads();
    if (threadIdx.x == 0) d_len[b] = cnt;
    for (int i = threadIdx.x; i < 132; i += blockDim.x){
        d_hbuf[0][0][b][i] = 0u;
        d_hbuf[0][1][b][i] = 0u;
        d_hbuf[1][0][b][i] = 0u;
        d_hbuf[1][1][b][i] = 0u;
    }
}

// ---------------------------------------------------------------------------
// Kernel 2: vocab projection GEMM via tf32 mma (unchanged from R4)
// ---------------------------------------------------------------------------
__global__ void __launch_bounds__(256, 2)
k_vgemm(const float* __restrict__ emb,
        const float* __restrict__ Wfw, const float* __restrict__ bfw,
        const float* __restrict__ Wbw, const float* __restrict__ bbw){
    __shared__ unsigned As[16][132];   // [k][m] tf32
    __shared__ unsigned Bs[16][132];   // [k][n] tf32
    int nx  = blockIdx.x;
    int dir = nx >> 3;
    int n0  = (nx & 7) * 128;
    int m0  = blockIdx.y * 128;
    const float* __restrict__ Wg = dir ? Wbw : Wfw;
    const float* __restrict__ bg = dir ? bbw : bfw;

    int t    = threadIdx.x;
    int lane = t & 31;
    int w    = t >> 5;
    int wm   = w & 1;
    int wn   = w >> 1;

    float acc[4][4][4] = {};

    for (int k0 = 0; k0 < 304; k0 += 16){
        {
            int kk = (t & 3) * 4;
            #pragma unroll
            for (int i = 0; i < 2; i++){
                int m  = (t >> 2) + i*64;
                int gm = m0 + m;
                float4 v = make_float4(0.f,0.f,0.f,0.f);
                if (gm < VOCAB && (k0 + kk + 4) <= EMB)
                    v = *(const float4*)&emb[(size_t)gm*EMB + k0 + kk];
                As[kk+0][m] = f2tf(v.x);
                As[kk+1][m] = f2tf(v.y);
                As[kk+2][m] = f2tf(v.z);
                As[kk+3][m] = f2tf(v.w);
            }
        }
        {
            int kk = t >> 4;
            int nn = (t & 15) * 8;
            float4 v0 = make_float4(0.f,0.f,0.f,0.f);
            float4 v1 = make_float4(0.f,0.f,0.f,0.f);
            if (k0 + kk < EMB){
                v0 = *(const float4*)&Wg[(size_t)(k0 + kk)*GATES + n0 + nn];
                v1 = *(const float4*)&Wg[(size_t)(k0 + kk)*GATES + n0 + nn + 4];
            }
            Bs[kk][nn+0] = f2tf(v0.x); Bs[kk][nn+1] = f2tf(v0.y);
            Bs[kk][nn+2] = f2tf(v0.z); Bs[kk][nn+3] = f2tf(v0.w);
            Bs[kk][nn+4] = f2tf(v1.x); Bs[kk][nn+5] = f2tf(v1.y);
            Bs[kk][nn+6] = f2tf(v1.z); Bs[kk][nn+7] = f2tf(v1.w);
        }
        __syncthreads();

        #pragma unroll
        for (int k8 = 0; k8 < 2; k8++){
            int k = k8*8 + (lane & 3);
            unsigned a[4][4], b[4][2];
            #pragma unroll
            for (int mi = 0; mi < 4; mi++){
                int row = wm*64 + mi*16 + (lane >> 2);
                a[mi][0] = As[k  ][row];
                a[mi][1] = As[k  ][row + 8];
                a[mi][2] = As[k+4][row];
                a[mi][3] = As[k+4][row + 8];
            }
            #pragma unroll
            for (int ni = 0; ni < 4; ni++){
                int n = wn*32 + ni*8 + (lane >> 2);
                b[ni][0] = Bs[k  ][n];
                b[ni][1] = Bs[k+4][n];
            }
            #pragma unroll
            for (int mi = 0; mi < 4; mi++)
                #pragma unroll
                for (int ni = 0; ni < 4; ni++)
                    asm volatile(
                        "mma.sync.aligned.m16n8k8.row.col.f32.tf32.tf32.f32 "
                        "{%0,%1,%2,%3},{%4,%5,%6,%7},{%8,%9},{%0,%1,%2,%3};"
                        : "+f"(acc[mi][ni][0]), "+f"(acc[mi][ni][1]),
                          "+f"(acc[mi][ni][2]), "+f"(acc[mi][ni][3])
                        : "r"(a[mi][0]), "r"(a[mi][1]), "r"(a[mi][2]), "r"(a[mi][3]),
                          "r"(b[ni][0]), "r"(b[ni][1]));
        }
        __syncthreads();
    }

    #pragma unroll
    for (int mi = 0; mi < 4; mi++){
        int rbase = m0 + wm*64 + mi*16 + (lane >> 2);
        #pragma unroll
        for (int ni = 0; ni < 4; ni++){
            int cbase = n0 + wn*32 + ni*8 + (lane & 3)*2;
            #pragma unroll
            for (int c = 0; c < 4; c++){
                int gm  = rbase + (c >> 1)*8;
                int col = cbase + (c & 1);
                if (gm >= VOCAB) continue;
                int g  = col >> 8;
                int hc = col & 255;
                d_proj[gm][dir*GATES + hc*4 + g] = acc[mi][ni][c] + bg[col];
            }
        }
    }
}

// ---------------------------------------------------------------------------
// Kernel 3: persistent bidirectional LSTM recurrence — fp16 tensor cores,
// cluster(8) = the 8 hcol-blocks sharing one (dir, batch-tile). h exchange
// via global L2, synchronized by barrier.cluster (release/acquire).
// ---------------------------------------------------------------------------
__global__ void __launch_bounds__(256, 1) __cluster_dims__(8, 1, 1)
k_rnn(const float* __restrict__ Wfw, const float* __restrict__ Wbw,
      const int* __restrict__ ids){
    extern __shared__ unsigned smem_u[];
    unsigned* sWb = smem_u;            // [4 gates][4 wg][16 kb][32 lanes][2] fp16 B frags
    unsigned* sh2 = smem_u + 16384;    // [32][132] fp16 pairs, k-permuted
    __shared__ int s_id[32];

    int tid = threadIdx.x;
    int bid = blockIdx.x;
    int dir = bid >> 6;
    int tl  = bid & 63;
    int b0  = (tl >> 3) * 32;
    int h0  = (tl & 7) * 32;          // cluster rank = hcol tile
    const float* __restrict__ Wg = dir ? Wbw : Wfw;

    int lane = tid & 31;
    int w    = tid >> 5;
    int mr   = w & 1;       // batch half
    int wg   = w >> 1;      // hid group of 8
    int gid  = lane >> 2;
    int qq   = lane & 3;

    // ---- Fill Wh fp16 B-fragments once ----
    // f = g<<12 | wg<<10 | kb<<6 | lane<<1 | s ; frag s at k = kb*16 + 2*(lane&3) + s*8
    for (int f = tid; f < 16384; f += 256){
        int s   = f & 1;
        int ln  = (f >> 1) & 31;
        int kb  = (f >> 6) & 15;
        int wgf = (f >> 10) & 3;
        int g   = (f >> 12) & 3;
        int k   = kb*16 + (ln & 3)*2 + s*8;
        int col = g*HID + h0 + wgf*8 + (ln >> 2);
        __half2 hv = __halves2half2(
            __float2half_rn(Wg[(EMB + k    )*GATES + col]),
            __float2half_rn(Wg[(EMB + k + 1)*GATES + col]));
        sWb[f] = *(unsigned*)&hv;
    }

    int rb0 = mr*16 + gid;      // block-local batch rows this thread owns
    int rb1 = rb0 + 8;
    int hc0 = wg*8 + qq*2;      // block-local hidden cols (hc0, hc0+1) — one fp16 pair
    int len0 = d_len[b0 + rb0];
    int len1 = d_len[b0 + rb1];
    float c_reg[4] = {0.f, 0.f, 0.f, 0.f};   // [rr*2+cc]
    float h_reg[4] = {0.f, 0.f, 0.f, 0.f};
    int   wslot = hslot(h0 + hc0);           // u32 index of this thread's h pair

    for (int t = 0; t < SEQT; t++){
        int cur = t & 1, nxt = cur ^ 1;
        int teff = dir ? (SEQT - 1 - t) : t;

        // token ids + stage h (L1-bypass loads; freshness guaranteed by cluster acquire)
        if (tid < 32) s_id[tid] = __ldcg(&ids[(b0 + tid)*SEQT + teff]);
        for (int idx = tid; idx < 32*33; idx += 256){
            int b = idx / 33, q = idx % 33;
            *(uint4*)&sh2[b*132 + q*4] =
                __ldcg((const uint4*)&d_hbuf[dir][cur][b0 + b][q*4]);
        }
        __syncthreads();

        // prefetch input-projection gathers (hidden under the MMA loop)
        float4 xz[2][2];
        {
            int id0 = s_id[rb0], id1 = s_id[rb1];
            const float* p0 = &d_proj[id0][dir*GATES];
            const float* p1 = &d_proj[id1][dir*GATES];
            xz[0][0] = *(const float4*)&p0[(h0 + hc0    )*4];
            xz[0][1] = *(const float4*)&p0[(h0 + hc0 + 1)*4];
            xz[1][0] = *(const float4*)&p1[(h0 + hc0    )*4];
            xz[1][1] = *(const float4*)&p1[(h0 + hc0 + 1)*4];
        }

        float acc[4][4];
        #pragma unroll
        for (int g = 0; g < 4; g++){
            acc[g][0]=0.f; acc[g][1]=0.f; acc[g][2]=0.f; acc[g][3]=0.f;
        }

        #pragma unroll
        for (int kb = 0; kb < 16; kb++){
            // A frags: aA = (a0,a2) from row rb0, aB = (a1,a3) from row rb1
            uint2 aA = *(const uint2*)&sh2[rb0*132 + kb*8 + qq*2];
            uint2 aB = *(const uint2*)&sh2[rb1*132 + kb*8 + qq*2];
            #pragma unroll
            for (int g = 0; g < 4; g++){
                uint2 bb = *(const uint2*)&sWb[g*4096 + wg*1024 + kb*64 + lane*2];
                asm volatile(
                    "mma.sync.aligned.m16n8k16.row.col.f32.f16.f16.f32 "
                    "{%0,%1,%2,%3},{%4,%5,%6,%7},{%8,%9},{%0,%1,%2,%3};"
                    : "+f"(acc[g][0]), "+f"(acc[g][1]), "+f"(acc[g][2]), "+f"(acc[g][3])
                    : "r"(aA.x), "r"(aB.x), "r"(aA.y), "r"(aB.y),
                      "r"(bb.x), "r"(bb.y));
            }
        }

        // elementwise LSTM cell on the 4 (b,hj) cells this thread owns
        #pragma unroll
        for (int rr = 0; rr < 2; rr++){
            int bl  = rr ? rb1 : rb0;
            int len = rr ? len1 : len0;
            bool valid = (teff < len);
            #pragma unroll
            for (int cc = 0; cc < 2; cc++){
                int ci = rr*2 + cc;
                float zi = acc[0][ci] + (cc ? xz[rr][1].x : xz[rr][0].x);
                float zj = acc[1][ci] + (cc ? xz[rr][1].y : xz[rr][0].y);
                float zf = acc[2][ci] + (cc ? xz[rr][1].z : xz[rr][0].z);
                float zo = acc[3][ci] + (cc ? xz[rr][1].w : xz[rr][0].w);
                float nc = c_reg[ci]*sigf(zf + 1.0f) + sigf(zi)*tanhfast(zj);
                float nh = tanhfast(nc)*sigf(zo);
                if (valid){ c_reg[ci] = nc; h_reg[ci] = nh; }
            }
            __half2 hv = __halves2half2(__float2half_rn(h_reg[rr*2]),
                                        __float2half_rn(h_reg[rr*2 + 1]));
            d_hbuf[dir][nxt][b0 + bl][wslot] = *(unsigned*)&hv;
        }

        // ---- cluster-wide step barrier (release/acquire: orders the h exchange) ----
        asm volatile("barrier.cluster.arrive.aligned;" ::: "memory");
        asm volatile("barrier.cluster.wait.aligned;" ::: "memory");
    }

    // write fp32 final hidden state
    #pragma unroll
    for (int rr = 0; rr < 2; rr++){
        int bl = rr ? rb1 : rb0;
        d_hfinal[dir][b0 + bl][h0 + hc0    ] = h_reg[rr*2];
        d_hfinal[dir][b0 + bl][h0 + hc0 + 1] = h_reg[rr*2 + 1];
    }
}

// ---------------------------------------------------------------------------
// Kernel 4: final projection scores = [h_fw | h_bw] @ W_out + b_out
// ---------------------------------------------------------------------------
__global__ void k_out(const float* __restrict__ Wout, const float* __restrict__ bout,
                      float* __restrict__ out){
    int b = blockIdx.x;
    int tid = threadIdx.x;
    float s0 = 0.0f, s1 = 0.0f;
    for (int k = tid; k < 512; k += 256){
        float v = (k < 256) ? d_hfinal[0][b][k] : d_hfinal[1][b][k - 256];
        s0 += v*Wout[2*k];
        s1 += v*Wout[2*k + 1];
    }
    #pragma unroll
    for (int o = 16; o; o >>= 1){
        s0 += __shfl_down_sync(0xffffffffu, s0, o);
        s1 += __shfl_down_sync(0xffffffffu, s1, o);
    }
    __shared__ float r0[8], r1[8];
    int w = tid >> 5;
    if ((tid & 31) == 0){ r0[w] = s0; r1[w] = s1; }
    __syncthreads();
    if (tid == 0){
        float t0 = bout[0], t1 = bout[1];
        #pragma unroll
        for (int i = 0; i < 8; i++){ t0 += r0[i]; t1 += r1[i]; }
        out[2*b]     = t0;
        out[2*b + 1] = t1;
    }
}

// ---------------------------------------------------------------------------
extern "C" void kernel_launch(void* const* d_in, const int* in_sizes, int n_in,
                              void* d_out, int out_size){
    const int*   ids  = (const int*)  d_in[0];
    const float* emb  = (const float*)d_in[1];
    const float* Wfw  = (const float*)d_in[2];
    const float* bfw  = (const float*)d_in[3];
    const float* Wbw  = (const float*)d_in[4];
    const float* bbw  = (const float*)d_in[5];
    const float* Wout = (const float*)d_in[6];
    const float* bout = (const float*)d_in[7];
    float* out = (float*)d_out;

    cudaFuncSetAttribute(k_rnn, cudaFuncAttributeMaxDynamicSharedMemorySize, SMEM_RNN);

    k_init<<<BATCH, 128>>>(ids);
    dim3 g2(16, (VOCAB + 127)/128);
    k_vgemm<<<g2, 256>>>(emb, Wfw, bfw, Wbw, bbw);
    k_rnn<<<NBLK, 256, SMEM_RNN>>>(Wfw, Wbw, ids);
    k_out<<<BATCH, 256>>>(Wout, bout, out);
}